// round 9
// baseline (speedup 1.0000x reference)
#include <cuda_runtime.h>

#define NB 16            // batch
#define NS 65            // segments per batch
#define NR 1040          // NB*NS rows
#define NW 256           // candidate positions per row
#define ND 128           // feature dim
#define T_PAD 2176       // padded time length of x
#define LSEQ 2048        // MAX_LEN_SEQ
#define MIN_SEG 32
#define NOUT (NB * LSEQ) // 32768 output rows
#define FULL 0xffffffffu

#define RUN_BLOCKS 1040
#define FILL_BLOCKS 64

__device__ int g_rowstart[NR + 1];
__device__ int g_offset[NR];
__device__ int g_L[1];

// Exact-boundary row count: smallest w in [0,NW] with floor(rn(w/sc)) >= Tm.
// w* lies within +-3 of Tm*sc; probe an 8-wide window with INDEPENDENT IEEE
// divides using the reference's exact predicate.
__device__ __forceinline__ int row_count(int Tm, float sc) {
    if (Tm <= 0) return 0;
    float wr = (float)Tm * sc;
    int wlo = (int)wr - 3;
    if (wlo < 0) wlo = 0;
    if (wlo >= NW) return NW;
    float fT = (float)Tm;
    int cnt = NW;
    #pragma unroll
    for (int j = 0; j < 8; j++) {
        int w = wlo + j;
        bool fail = (w < NW) && (floorf(__fdiv_rn((float)w, sc)) >= fT);
        if (fail && w < cnt) cnt = w;   // ascending -> min = first fail
    }
    return cnt;
}

// ---------------------------------------------------------------------------
// Setup (R6 version, proven): per-batch segment-offset warp-scans, per-row
// count via window probe, block exclusive scan via shfl. 1 block x 1024.
// ---------------------------------------------------------------------------
__global__ void __launch_bounds__(1024)
setup_kernel(const float* __restrict__ scales,
             const int* __restrict__ len_seq,
             const int* __restrict__ len_seg_raw) {
    __shared__ int sh_seg[NR];
    __shared__ int sh_off[NR];
    __shared__ int sh_ws[32];
    int tid  = threadIdx.x;
    int wid  = tid >> 5;
    int lane = tid & 31;

    for (int i = tid; i < NR; i += 1024) sh_seg[i] = len_seg_raw[i] + MIN_SEG;
    __syncthreads();

    if (wid < NB) {      // warp wb scans batch wb (65 elems, 3 chunks)
        int base = wid * NS;
        int carry = 0;
        #pragma unroll
        for (int c = 0; c < 3; c++) {
            int i = c * 32 + lane;
            int v = (i < NS) ? sh_seg[base + i] : 0;
            int s = v;
            #pragma unroll
            for (int o = 1; o < 32; o <<= 1) {
                int u = __shfl_up_sync(FULL, s, o);
                if (lane >= o) s += u;
            }
            if (i < NS) sh_off[base + i] = carry + s - v;   // exclusive
            carry += __shfl_sync(FULL, s, 31);
        }
    }
    __syncthreads();

    int a0 = 0, a1 = 0;
    int i0 = 2 * tid, i1 = 2 * tid + 1;
    if (i0 < NR) {
        int b = i0 / NS;
        a0 = row_count(min(sh_seg[i0] - 1, len_seq[b] - 1 - sh_off[i0]),
                       scales[i0] + 0.5f);
    }
    if (i1 < NR) {
        int b = i1 / NS;
        a1 = row_count(min(sh_seg[i1] - 1, len_seq[b] - 1 - sh_off[i1]),
                       scales[i1] + 0.5f);
    }

    int s = a0 + a1;
    int incl = s;
    #pragma unroll
    for (int o = 1; o < 32; o <<= 1) {
        int u = __shfl_up_sync(FULL, incl, o);
        if (lane >= o) incl += u;
    }
    if (lane == 31) sh_ws[wid] = incl;
    __syncthreads();
    if (wid == 0) {
        int ws = sh_ws[lane];
        #pragma unroll
        for (int o = 1; o < 32; o <<= 1) {
            int u = __shfl_up_sync(FULL, ws, o);
            if (lane >= o) ws += u;
        }
        sh_ws[lane] = ws;
    }
    __syncthreads();
    int warp_base = (wid > 0) ? sh_ws[wid - 1] : 0;
    incl += warp_base;
    int excl = incl - s;

    if (i0 < NR) { g_rowstart[i0] = excl;      g_offset[i0] = sh_off[i0]; }
    if (i1 < NR) { g_rowstart[i1] = excl + a0; g_offset[i1] = sh_off[i1]; }
    if (tid == 519) {                   // rows 1038,1039 -> incl = total
        g_rowstart[NR] = incl;
        g_L[0] = incl / NB;
    }
}

// ---------------------------------------------------------------------------
// Run-gather: blocks [0,1040): block = segment row r; warp wib handles
// k in [32*wib, 32*wib+32) of the row's prefix run. Destination (bo,t)
// tracked incrementally (one int div per warp). Blocks [1040, 1104): zero
// fill for t >= L (disjoint from run writes).
// ---------------------------------------------------------------------------
__global__ void __launch_bounds__(256)
run_gather_kernel(const float* __restrict__ x,
                  const float* __restrict__ scales,
                  float* __restrict__ out) {
#if __CUDA_ARCH__ >= 900
    cudaGridDependencySynchronize();   // PDL: wait for setup results
#endif
    int lane = threadIdx.x & 31;
    int wib  = threadIdx.x >> 5;
    int L    = g_L[0];

    if (blockIdx.x < RUN_BLOCKS) {
        if (L <= 0) return;
        int r   = blockIdx.x;
        int g0  = g_rowstart[r];
        int cnt = g_rowstart[r + 1] - g0;
        int k0  = wib << 5;
        if (k0 >= cnt) return;
        int kend = min(k0 + 32, cnt);

        int base = (r / NS) * T_PAD + g_offset[r];
        float sc = scales[r] + 0.5f;

        int g  = g0 + k0;
        int bo = g / L;              // one division per warp
        int t  = g - bo * L;

        for (int k = k0; k < kend; k++) {
            if (bo >= NB) break;     // truncated remainder (g >= NB*L)
            float fs = __fdiv_rn((float)k, sc);
            float fl = floorf(fs);
            float lam = fs - fl;
            const float4* p = (const float4*)(x + (size_t)(base + (int)fl) * ND);
            float4 a = p[lane];
            float4 c = p[lane + 32];
            float om = 1.0f - lam;
            float4 y;
            y.x = om * a.x + lam * c.x;
            y.y = om * a.y + lam * c.y;
            y.z = om * a.z + lam * c.z;
            y.w = om * a.w + lam * c.w;
            if (t < LSEQ)
                __stcs((float4*)(out + (size_t)(bo * LSEQ + t) * ND) + lane, y);
            if (++t == L) { t = 0; bo++; }
        }
    } else {
        // zero fill: warp per output row, rows with t >= L
        float4 z = make_float4(0.f, 0.f, 0.f, 0.f);
        int warp0 = (blockIdx.x - RUN_BLOCKS) * 8 + wib;
        for (int row = warp0; row < NOUT; row += FILL_BLOCKS * 8) {
            int t = row & (LSEQ - 1);
            if (t >= L)
                __stcs((float4*)(out + (size_t)row * ND) + lane, z);
        }
    }
}

static inline void launch_pdl(void* fn, dim3 grid, dim3 block, void** args) {
    cudaLaunchConfig_t cfg = {};
    cfg.gridDim = grid;
    cfg.blockDim = block;
    cfg.dynamicSmemBytes = 0;
    cfg.stream = 0;
    cudaLaunchAttribute attr[1];
    attr[0].id = cudaLaunchAttributeProgrammaticStreamSerialization;
    attr[0].val.programmaticStreamSerializationAllowed = 1;
    cfg.attrs = attr;
    cfg.numAttrs = 1;
    cudaLaunchKernelExC(&cfg, fn, args);
}

extern "C" void kernel_launch(void* const* d_in, const int* in_sizes, int n_in,
                              void* d_out, int out_size) {
    const float* x           = (const float*)d_in[0];
    const float* scales      = (const float*)d_in[1];
    const int*   len_seq     = (const int*)d_in[2];
    const int*   len_seg_raw = (const int*)d_in[3];
    float* out = (float*)d_out;

    setup_kernel<<<1, 1024>>>(scales, len_seq, len_seg_raw);

    void* args[] = { (void*)&x, (void*)&scales, (void*)&out };
    launch_pdl((void*)run_gather_kernel,
               dim3(RUN_BLOCKS + FILL_BLOCKS), dim3(256), args);
}

// round 10
// speedup vs baseline: 1.2765x; 1.2765x over previous
#include <cuda_runtime.h>

#define NB 16            // batch
#define NS 65            // segments per batch
#define NR 1040          // NB*NS rows
#define NW 256           // candidate positions per row
#define ND 128           // feature dim
#define T_PAD 2176       // padded time length of x
#define LSEQ 2048        // MAX_LEN_SEQ
#define MIN_SEG 32
#define NOUT (NB * LSEQ) // 32768 output rows
#define FULL 0xffffffffu

__device__ int g_rowstart[NR + 1];
__device__ int g_offset[NR];
__device__ int g_L[1];

// Exact-boundary row count: smallest w in [0,NW] with floor(rn(w/sc)) >= Tm.
// w* lies within +-3 of Tm*sc; probe an 8-wide window with INDEPENDENT IEEE
// divides using the reference's exact predicate.
__device__ __forceinline__ int row_count(int Tm, float sc) {
    if (Tm <= 0) return 0;
    float wr = (float)Tm * sc;
    int wlo = (int)wr - 3;
    if (wlo < 0) wlo = 0;
    if (wlo >= NW) return NW;
    float fT = (float)Tm;
    int cnt = NW;
    #pragma unroll
    for (int j = 0; j < 8; j++) {
        int w = wlo + j;
        bool fail = (w < NW) && (floorf(__fdiv_rn((float)w, sc)) >= fT);
        if (fail && w < cnt) cnt = w;   // ascending -> min = first fail
    }
    return cnt;
}

// ---------------------------------------------------------------------------
// Setup (R6 version, proven): per-batch segment-offset warp-scans, per-row
// count via window probe, block exclusive scan via shfl. 1 block x 1024.
// ---------------------------------------------------------------------------
__global__ void __launch_bounds__(1024)
setup_kernel(const float* __restrict__ scales,
             const int* __restrict__ len_seq,
             const int* __restrict__ len_seg_raw) {
    __shared__ int sh_seg[NR];
    __shared__ int sh_off[NR];
    __shared__ int sh_ws[32];
    int tid  = threadIdx.x;
    int wid  = tid >> 5;
    int lane = tid & 31;

    for (int i = tid; i < NR; i += 1024) sh_seg[i] = len_seg_raw[i] + MIN_SEG;
    __syncthreads();

    if (wid < NB) {      // warp wb scans batch wb (65 elems, 3 chunks)
        int base = wid * NS;
        int carry = 0;
        #pragma unroll
        for (int c = 0; c < 3; c++) {
            int i = c * 32 + lane;
            int v = (i < NS) ? sh_seg[base + i] : 0;
            int s = v;
            #pragma unroll
            for (int o = 1; o < 32; o <<= 1) {
                int u = __shfl_up_sync(FULL, s, o);
                if (lane >= o) s += u;
            }
            if (i < NS) sh_off[base + i] = carry + s - v;   // exclusive
            carry += __shfl_sync(FULL, s, 31);
        }
    }
    __syncthreads();

    int a0 = 0, a1 = 0;
    int i0 = 2 * tid, i1 = 2 * tid + 1;
    if (i0 < NR) {
        int b = i0 / NS;
        a0 = row_count(min(sh_seg[i0] - 1, len_seq[b] - 1 - sh_off[i0]),
                       scales[i0] + 0.5f);
    }
    if (i1 < NR) {
        int b = i1 / NS;
        a1 = row_count(min(sh_seg[i1] - 1, len_seq[b] - 1 - sh_off[i1]),
                       scales[i1] + 0.5f);
    }

    int s = a0 + a1;
    int incl = s;
    #pragma unroll
    for (int o = 1; o < 32; o <<= 1) {
        int u = __shfl_up_sync(FULL, incl, o);
        if (lane >= o) incl += u;
    }
    if (lane == 31) sh_ws[wid] = incl;
    __syncthreads();
    if (wid == 0) {
        int ws = sh_ws[lane];
        #pragma unroll
        for (int o = 1; o < 32; o <<= 1) {
            int u = __shfl_up_sync(FULL, ws, o);
            if (lane >= o) ws += u;
        }
        sh_ws[lane] = ws;
    }
    __syncthreads();
    int warp_base = (wid > 0) ? sh_ws[wid - 1] : 0;
    incl += warp_base;
    int excl = incl - s;

    if (i0 < NR) { g_rowstart[i0] = excl;      g_offset[i0] = sh_off[i0]; }
    if (i1 < NR) { g_rowstart[i1] = excl + a0; g_offset[i1] = sh_off[i1]; }
    if (tid == 519) {                   // rows 1038,1039 -> incl = total
        g_rowstart[NR] = incl;
        g_L[0] = incl / NB;
    }
}

// ---------------------------------------------------------------------------
// Search-gather: 4 output rows per warp. Lanes 0-3 run independent binary
// searches over g_rowstart (L1-hot, 4KB) in parallel; 2 shfl broadcasts; then
// 8 independent 512B x-row loads, lerp, streaming stores. No table, no expand.
// ---------------------------------------------------------------------------
__global__ void __launch_bounds__(256)
gather_kernel(const float* __restrict__ x,
              const float* __restrict__ scales,
              float* __restrict__ out) {
#if __CUDA_ARCH__ >= 900
    cudaGridDependencySynchronize();   // PDL: wait for setup results
#endif
    int warp = (blockIdx.x * blockDim.x + threadIdx.x) >> 5;
    int lane = threadIdx.x & 31;
    int gid0 = warp << 2;              // 4 rows per warp
    if (gid0 >= NOUT) return;
    int L = g_L[0];

    // lanes 0-3: independent searches for rows gid0..gid0+3
    unsigned pack = 0;                 // base(16) | w(8)<<16 | valid<<24
    float sc = 1.0f;
    if (lane < 4) {
        int gid = gid0 + lane;
        int t   = gid & (LSEQ - 1);
        int b   = gid >> 11;
        if (t < L) {
            int g = b * L + t;
            int lo = 0, hi = NR;
            while (hi - lo > 1) {
                int mid = (lo + hi) >> 1;
                if (g_rowstart[mid] <= g) lo = mid; else hi = mid;
            }
            int w    = g - g_rowstart[lo];
            int base = (lo / NS) * T_PAD + g_offset[lo];
            pack = (unsigned)base | ((unsigned)w << 16) | (1u << 24);
            sc   = scales[lo] + 0.5f;
        }
    }

    unsigned pk[4];
    float    scj[4];
    #pragma unroll
    for (int j = 0; j < 4; j++) {
        pk[j]  = __shfl_sync(FULL, pack, j);
        scj[j] = __uint_as_float(__shfl_sync(FULL, __float_as_uint(sc), j));
    }

    bool v[4];
    float lam[4];
    const float4* p[4];
    #pragma unroll
    for (int j = 0; j < 4; j++) {
        v[j]   = (pk[j] >> 24) & 1u;
        lam[j] = 0.f;
        p[j]   = (const float4*)x;
        if (v[j]) {
            int base = (int)(pk[j] & 0xFFFFu);
            int w    = (int)((pk[j] >> 16) & 0xFFu);
            float fs = __fdiv_rn((float)w, scj[j]);
            float fl = floorf(fs);
            lam[j] = fs - fl;
            p[j] = (const float4*)(x + (size_t)(base + (int)fl) * ND);
        }
    }

    // all 8 independent LDG.128 in flight before consumption
    float4 a[4], c[4];
    #pragma unroll
    for (int j = 0; j < 4; j++) {
        if (v[j]) { a[j] = p[j][lane]; c[j] = p[j][lane + 32]; }
    }

    #pragma unroll
    for (int j = 0; j < 4; j++) {
        float4 y = make_float4(0.f, 0.f, 0.f, 0.f);
        if (v[j]) {
            float om = 1.0f - lam[j];
            y.x = om * a[j].x + lam[j] * c[j].x;
            y.y = om * a[j].y + lam[j] * c[j].y;
            y.z = om * a[j].z + lam[j] * c[j].z;
            y.w = om * a[j].w + lam[j] * c[j].w;
        }
        __stcs((float4*)(out + (size_t)(gid0 + j) * ND) + lane, y);
    }
}

static inline void launch_pdl(void* fn, dim3 grid, dim3 block, void** args) {
    cudaLaunchConfig_t cfg = {};
    cfg.gridDim = grid;
    cfg.blockDim = block;
    cfg.dynamicSmemBytes = 0;
    cfg.stream = 0;
    cudaLaunchAttribute attr[1];
    attr[0].id = cudaLaunchAttributeProgrammaticStreamSerialization;
    attr[0].val.programmaticStreamSerializationAllowed = 1;
    cfg.attrs = attr;
    cfg.numAttrs = 1;
    cudaLaunchKernelExC(&cfg, fn, args);
}

extern "C" void kernel_launch(void* const* d_in, const int* in_sizes, int n_in,
                              void* d_out, int out_size) {
    const float* x           = (const float*)d_in[0];
    const float* scales      = (const float*)d_in[1];
    const int*   len_seq     = (const int*)d_in[2];
    const int*   len_seg_raw = (const int*)d_in[3];
    float* out = (float*)d_out;

    setup_kernel<<<1, 1024>>>(scales, len_seq, len_seg_raw);

    void* args[] = { (void*)&x, (void*)&scales, (void*)&out };
    launch_pdl((void*)gather_kernel, dim3(NOUT / 4 / 8), dim3(256), args);
}

// round 11
// speedup vs baseline: 1.4450x; 1.1320x over previous
#include <cuda_runtime.h>

#define NB 16            // batch
#define NS 65            // segments per batch
#define NR 1040          // NB*NS rows
#define NW 256           // candidate positions per row
#define ND 128           // feature dim
#define T_PAD 2176       // padded time length of x
#define LSEQ 2048        // MAX_LEN_SEQ
#define MIN_SEG 32
#define NOUT (NB * LSEQ) // 32768 output rows
#define FULL 0xffffffffu

__device__ int   g_rowstart[NR + 1];
__device__ uint2 g_desc[NR];      // .x = base row in x ( (r/NS)*T_PAD+offset ), .y = scale bits
__device__ int   g_L[1];

// Exact-boundary row count: smallest w in [0,NW] with floor(rn(w/sc)) >= Tm.
// w* lies within +-3 of Tm*sc; probe an 8-wide window with INDEPENDENT IEEE
// divides using the reference's exact predicate.
__device__ __forceinline__ int row_count(int Tm, float sc) {
    if (Tm <= 0) return 0;
    float wr = (float)Tm * sc;
    int wlo = (int)wr - 3;
    if (wlo < 0) wlo = 0;
    if (wlo >= NW) return NW;
    float fT = (float)Tm;
    int cnt = NW;
    #pragma unroll
    for (int j = 0; j < 8; j++) {
        int w = wlo + j;
        bool fail = (w < NW) && (floorf(__fdiv_rn((float)w, sc)) >= fT);
        if (fail && w < cnt) cnt = w;   // ascending -> min = first fail
    }
    return cnt;
}

// ---------------------------------------------------------------------------
// Setup: per-batch segment-offset warp-scans, per-row count (window probe),
// block exclusive scan via shfl, per-row descriptor write. 1 block x 1024.
// ---------------------------------------------------------------------------
__global__ void __launch_bounds__(1024)
setup_kernel(const float* __restrict__ scales,
             const int* __restrict__ len_seq,
             const int* __restrict__ len_seg_raw) {
    __shared__ int sh_seg[NR];
    __shared__ int sh_off[NR];
    __shared__ int sh_ws[32];
    int tid  = threadIdx.x;
    int wid  = tid >> 5;
    int lane = tid & 31;

    for (int i = tid; i < NR; i += 1024) sh_seg[i] = len_seg_raw[i] + MIN_SEG;
    __syncthreads();

    if (wid < NB) {      // warp wb scans batch wb (65 elems, 3 chunks)
        int base = wid * NS;
        int carry = 0;
        #pragma unroll
        for (int c = 0; c < 3; c++) {
            int i = c * 32 + lane;
            int v = (i < NS) ? sh_seg[base + i] : 0;
            int s = v;
            #pragma unroll
            for (int o = 1; o < 32; o <<= 1) {
                int u = __shfl_up_sync(FULL, s, o);
                if (lane >= o) s += u;
            }
            if (i < NS) sh_off[base + i] = carry + s - v;   // exclusive
            carry += __shfl_sync(FULL, s, 31);
        }
    }
    __syncthreads();

    float sc0 = 0.f, sc1 = 0.f;
    int a0 = 0, a1 = 0;
    int i0 = 2 * tid, i1 = 2 * tid + 1;
    if (i0 < NR) {
        int b = i0 / NS;
        sc0 = scales[i0] + 0.5f;
        a0 = row_count(min(sh_seg[i0] - 1, len_seq[b] - 1 - sh_off[i0]), sc0);
    }
    if (i1 < NR) {
        int b = i1 / NS;
        sc1 = scales[i1] + 0.5f;
        a1 = row_count(min(sh_seg[i1] - 1, len_seq[b] - 1 - sh_off[i1]), sc1);
    }

    int s = a0 + a1;
    int incl = s;
    #pragma unroll
    for (int o = 1; o < 32; o <<= 1) {
        int u = __shfl_up_sync(FULL, incl, o);
        if (lane >= o) incl += u;
    }
    if (lane == 31) sh_ws[wid] = incl;
    __syncthreads();
    if (wid == 0) {
        int ws = sh_ws[lane];
        #pragma unroll
        for (int o = 1; o < 32; o <<= 1) {
            int u = __shfl_up_sync(FULL, ws, o);
            if (lane >= o) ws += u;
        }
        sh_ws[lane] = ws;
    }
    __syncthreads();
    int warp_base = (wid > 0) ? sh_ws[wid - 1] : 0;
    incl += warp_base;
    int excl = incl - s;

    if (i0 < NR) {
        g_rowstart[i0] = excl;
        g_desc[i0] = make_uint2((unsigned)((i0 / NS) * T_PAD + sh_off[i0]),
                                __float_as_uint(sc0));
    }
    if (i1 < NR) {
        g_rowstart[i1] = excl + a0;
        g_desc[i1] = make_uint2((unsigned)((i1 / NS) * T_PAD + sh_off[i1]),
                                __float_as_uint(sc1));
    }
    if (tid == 519) {                   // rows 1038,1039 -> incl = total
        g_rowstart[NR] = incl;
        g_L[0] = incl / NB;
    }
}

// Warp-cooperative 2-round search: r = max{ r in [0,NR) : rowstart[r] <= g },
// also returns rowstart[r] (via shfl from the winning lane, no extra load).
__device__ __forceinline__ void warp_find(int g, int lane, int& r, int& rs) {
    int i1 = lane * 33;                    // max 1023 < NR
    int v1 = g_rowstart[i1];
    unsigned m1 = __ballot_sync(FULL, v1 <= g);   // lane0 always set (rowstart[0]=0)
    int h1 = 31 - __clz(m1);
    int b0 = h1 * 33;
    int i2 = b0 + 1 + lane;
    if (i2 > NR) i2 = NR;                  // rowstart[NR] = total > g
    int v2 = g_rowstart[i2];
    unsigned m2 = __ballot_sync(FULL, v2 <= g);
    if (m2) {
        int h2 = 31 - __clz(m2);
        r  = b0 + 1 + h2;
        rs = __shfl_sync(FULL, v2, h2);
    } else {
        r  = b0;
        rs = __shfl_sync(FULL, v1, h1);
    }
}

// ---------------------------------------------------------------------------
// Gather: 2 output rows per warp. Warp-parallel search (2 dependent loads),
// row-0 x loads issued before row-1 search to overlap. Streaming stores.
// ---------------------------------------------------------------------------
__global__ void __launch_bounds__(256)
gather_kernel(const float* __restrict__ x, float* __restrict__ out) {
#if __CUDA_ARCH__ >= 900
    cudaGridDependencySynchronize();   // PDL: wait for setup results
#endif
    int warp = (blockIdx.x * blockDim.x + threadIdx.x) >> 5;
    int lane = threadIdx.x & 31;
    int gid0 = warp << 1;
    if (gid0 >= NOUT) return;
    int L = g_L[0];

    // row 0
    int t0 = gid0 & (LSEQ - 1);
    int b0 = gid0 >> 11;
    bool v0 = (t0 < L);                 // warp-uniform
    float lam0 = 0.f;
    float4 a0, c0;
    if (v0) {
        int g = b0 * L + t0;
        int r, rs;
        warp_find(g, lane, r, rs);
        uint2 d = g_desc[r];
        int w = g - rs;
        float fs = __fdiv_rn((float)w, __uint_as_float(d.y));
        float fl = floorf(fs);
        lam0 = fs - fl;
        const float4* p = (const float4*)(x + (size_t)((int)d.x + (int)fl) * ND);
        a0 = p[lane]; c0 = p[lane + 32];    // in flight during row-1 search
    }

    // row 1
    int gid1 = gid0 + 1;
    int t1 = gid1 & (LSEQ - 1);
    int b1 = gid1 >> 11;
    bool v1 = (t1 < L);
    float lam1 = 0.f;
    float4 a1, c1;
    if (v1) {
        int g = b1 * L + t1;
        int r, rs;
        warp_find(g, lane, r, rs);
        uint2 d = g_desc[r];
        int w = g - rs;
        float fs = __fdiv_rn((float)w, __uint_as_float(d.y));
        float fl = floorf(fs);
        lam1 = fs - fl;
        const float4* p = (const float4*)(x + (size_t)((int)d.x + (int)fl) * ND);
        a1 = p[lane]; c1 = p[lane + 32];
    }

    float4 y0 = make_float4(0.f, 0.f, 0.f, 0.f);
    float4 y1 = y0;
    if (v0) {
        float om = 1.0f - lam0;
        y0.x = om * a0.x + lam0 * c0.x;  y0.y = om * a0.y + lam0 * c0.y;
        y0.z = om * a0.z + lam0 * c0.z;  y0.w = om * a0.w + lam0 * c0.w;
    }
    if (v1) {
        float om = 1.0f - lam1;
        y1.x = om * a1.x + lam1 * c1.x;  y1.y = om * a1.y + lam1 * c1.y;
        y1.z = om * a1.z + lam1 * c1.z;  y1.w = om * a1.w + lam1 * c1.w;
    }
    __stcs((float4*)(out + (size_t)gid0 * ND) + lane, y0);
    __stcs((float4*)(out + (size_t)gid1 * ND) + lane, y1);
}

static inline void launch_pdl(void* fn, dim3 grid, dim3 block, void** args) {
    cudaLaunchConfig_t cfg = {};
    cfg.gridDim = grid;
    cfg.blockDim = block;
    cfg.dynamicSmemBytes = 0;
    cfg.stream = 0;
    cudaLaunchAttribute attr[1];
    attr[0].id = cudaLaunchAttributeProgrammaticStreamSerialization;
    attr[0].val.programmaticStreamSerializationAllowed = 1;
    cfg.attrs = attr;
    cfg.numAttrs = 1;
    cudaLaunchKernelExC(&cfg, fn, args);
}

extern "C" void kernel_launch(void* const* d_in, const int* in_sizes, int n_in,
                              void* d_out, int out_size) {
    const float* x           = (const float*)d_in[0];
    const float* scales      = (const float*)d_in[1];
    const int*   len_seq     = (const int*)d_in[2];
    const int*   len_seg_raw = (const int*)d_in[3];
    float* out = (float*)d_out;

    setup_kernel<<<1, 1024>>>(scales, len_seq, len_seg_raw);

    void* args[] = { (void*)&x, (void*)&out };
    launch_pdl((void*)gather_kernel, dim3(NOUT / 2 / 8), dim3(256), args);
}

// round 12
// speedup vs baseline: 1.4775x; 1.0225x over previous
#include <cuda_runtime.h>

#define NB 16            // batch
#define NS 65            // segments per batch
#define NR 1040          // NB*NS rows
#define NW 256           // candidate positions per row
#define ND 128           // feature dim
#define T_PAD 2176       // padded time length of x
#define LSEQ 2048        // MAX_LEN_SEQ
#define MIN_SEG 32
#define NOUT (NB * LSEQ) // 32768 output rows
#define FULL 0xffffffffu

__device__ int   g_rowstart[NR + 1];
__device__ uint2 g_desc[NR];      // .x = base row in x ((r/NS)*T_PAD+offset), .y = scale bits
__device__ int   g_L[1];

// Exact-boundary row count: smallest w in [0,NW] with floor(rn(w/sc)) >= Tm.
// w* lies within +-3 of Tm*sc; probe an 8-wide window with INDEPENDENT IEEE
// divides using the reference's exact predicate.
__device__ __forceinline__ int row_count(int Tm, float sc) {
    if (Tm <= 0) return 0;
    float wr = (float)Tm * sc;
    int wlo = (int)wr - 3;
    if (wlo < 0) wlo = 0;
    if (wlo >= NW) return NW;
    float fT = (float)Tm;
    int cnt = NW;
    #pragma unroll
    for (int j = 0; j < 8; j++) {
        int w = wlo + j;
        bool fail = (w < NW) && (floorf(__fdiv_rn((float)w, sc)) >= fT);
        if (fail && w < cnt) cnt = w;   // ascending -> min = first fail
    }
    return cnt;
}

// ---------------------------------------------------------------------------
// Setup (proven): per-batch segment-offset warp-scans, per-row count via
// window probe, block exclusive scan via shfl, descriptor write. 1x1024.
// ---------------------------------------------------------------------------
__global__ void __launch_bounds__(1024)
setup_kernel(const float* __restrict__ scales,
             const int* __restrict__ len_seq,
             const int* __restrict__ len_seg_raw) {
    __shared__ int sh_seg[NR];
    __shared__ int sh_off[NR];
    __shared__ int sh_ws[32];
    int tid  = threadIdx.x;
    int wid  = tid >> 5;
    int lane = tid & 31;

    for (int i = tid; i < NR; i += 1024) sh_seg[i] = len_seg_raw[i] + MIN_SEG;
    __syncthreads();

    if (wid < NB) {      // warp wb scans batch wb (65 elems, 3 chunks)
        int base = wid * NS;
        int carry = 0;
        #pragma unroll
        for (int c = 0; c < 3; c++) {
            int i = c * 32 + lane;
            int v = (i < NS) ? sh_seg[base + i] : 0;
            int s = v;
            #pragma unroll
            for (int o = 1; o < 32; o <<= 1) {
                int u = __shfl_up_sync(FULL, s, o);
                if (lane >= o) s += u;
            }
            if (i < NS) sh_off[base + i] = carry + s - v;   // exclusive
            carry += __shfl_sync(FULL, s, 31);
        }
    }
    __syncthreads();

    float sc0 = 0.f, sc1 = 0.f;
    int a0 = 0, a1 = 0;
    int i0 = 2 * tid, i1 = 2 * tid + 1;
    if (i0 < NR) {
        int b = i0 / NS;
        sc0 = scales[i0] + 0.5f;
        a0 = row_count(min(sh_seg[i0] - 1, len_seq[b] - 1 - sh_off[i0]), sc0);
    }
    if (i1 < NR) {
        int b = i1 / NS;
        sc1 = scales[i1] + 0.5f;
        a1 = row_count(min(sh_seg[i1] - 1, len_seq[b] - 1 - sh_off[i1]), sc1);
    }

    int s = a0 + a1;
    int incl = s;
    #pragma unroll
    for (int o = 1; o < 32; o <<= 1) {
        int u = __shfl_up_sync(FULL, incl, o);
        if (lane >= o) incl += u;
    }
    if (lane == 31) sh_ws[wid] = incl;
    __syncthreads();
    if (wid == 0) {
        int ws = sh_ws[lane];
        #pragma unroll
        for (int o = 1; o < 32; o <<= 1) {
            int u = __shfl_up_sync(FULL, ws, o);
            if (lane >= o) ws += u;
        }
        sh_ws[lane] = ws;
    }
    __syncthreads();
    int warp_base = (wid > 0) ? sh_ws[wid - 1] : 0;
    incl += warp_base;
    int excl = incl - s;

    if (i0 < NR) {
        g_rowstart[i0] = excl;
        g_desc[i0] = make_uint2((unsigned)((i0 / NS) * T_PAD + sh_off[i0]),
                                __float_as_uint(sc0));
    }
    if (i1 < NR) {
        g_rowstart[i1] = excl + a0;
        g_desc[i1] = make_uint2((unsigned)((i1 / NS) * T_PAD + sh_off[i1]),
                                __float_as_uint(sc1));
    }
    if (tid == 519) {                   // rows 1038,1039 -> incl = total
        g_rowstart[NR] = incl;
        g_L[0] = incl / NB;
    }
}

// Warp-cooperative 2-round search: r = max{ r in [0,NR) : rowstart[r] <= g },
// also returns rowstart[r] (shfl from winning lane).
__device__ __forceinline__ void warp_find(int g, int lane, int& r, int& rs) {
    int i1 = lane * 33;                    // max 1023 < NR
    int v1 = g_rowstart[i1];
    unsigned m1 = __ballot_sync(FULL, v1 <= g);   // lane0 always set
    int h1 = 31 - __clz(m1);
    int b0 = h1 * 33;
    int i2 = b0 + 1 + lane;
    if (i2 > NR) i2 = NR;                  // rowstart[NR] = total > g
    int v2 = g_rowstart[i2];
    unsigned m2 = __ballot_sync(FULL, v2 <= g);
    if (m2) {
        int h2 = 31 - __clz(m2);
        r  = b0 + 1 + h2;
        rs = __shfl_sync(FULL, v2, h2);
    } else {
        r  = b0;
        rs = __shfl_sync(FULL, v1, h1);
    }
}

// ---------------------------------------------------------------------------
// Gather: 2 output rows per warp (same batch; g1 = g0+1). One warp_find for
// the pair; row 1 reuses it unless a (rare) segment-row crossing occurs.
// ---------------------------------------------------------------------------
__global__ void __launch_bounds__(256)
gather_kernel(const float* __restrict__ x, float* __restrict__ out) {
#if __CUDA_ARCH__ >= 900
    cudaGridDependencySynchronize();   // PDL: wait for setup results
#endif
    int warp = (blockIdx.x * blockDim.x + threadIdx.x) >> 5;
    int lane = threadIdx.x & 31;
    int gid0 = warp << 1;
    if (gid0 >= NOUT) return;
    int L = g_L[0];

    int t0 = gid0 & (LSEQ - 1);        // gid0 even => pair shares batch b
    int b  = gid0 >> 11;
    bool v0 = (t0 < L);
    bool v1 = (t0 + 1 < L);

    float lam0 = 0.f, lam1 = 0.f;
    float4 a0, c0, a1, c1;
    if (v0) {
        int g0 = b * L + t0;
        int r0, rs0;
        warp_find(g0, lane, r0, rs0);
        int nxt = g_rowstart[r0 + 1];          // L1-hot, issued early
        uint2 d0 = g_desc[r0];
        {
            int w = g0 - rs0;
            float fs = __fdiv_rn((float)w, __uint_as_float(d0.y));
            float fl = floorf(fs);
            lam0 = fs - fl;
            const float4* p = (const float4*)(x + (size_t)((int)d0.x + (int)fl) * ND);
            a0 = p[lane]; c0 = p[lane + 32];   // in flight during row-1 setup
        }
        if (v1) {
            int g1 = g0 + 1;
            int r1, rs1; uint2 d1;
            if (nxt <= g1) {                   // crossing (rare): full search
                warp_find(g1, lane, r1, rs1);
                d1 = g_desc[r1];
            } else {                           // same segment row (~98%)
                r1 = r0; rs1 = rs0; d1 = d0;
            }
            int w = g1 - rs1;
            float fs = __fdiv_rn((float)w, __uint_as_float(d1.y));
            float fl = floorf(fs);
            lam1 = fs - fl;
            const float4* p = (const float4*)(x + (size_t)((int)d1.x + (int)fl) * ND);
            a1 = p[lane]; c1 = p[lane + 32];
        }
    }

    float4 y0 = make_float4(0.f, 0.f, 0.f, 0.f);
    float4 y1 = y0;
    if (v0) {
        float om = 1.0f - lam0;
        y0.x = om * a0.x + lam0 * c0.x;  y0.y = om * a0.y + lam0 * c0.y;
        y0.z = om * a0.z + lam0 * c0.z;  y0.w = om * a0.w + lam0 * c0.w;
    }
    if (v1) {
        float om = 1.0f - lam1;
        y1.x = om * a1.x + lam1 * c1.x;  y1.y = om * a1.y + lam1 * c1.y;
        y1.z = om * a1.z + lam1 * c1.z;  y1.w = om * a1.w + lam1 * c1.w;
    }
    __stcs((float4*)(out + (size_t)gid0 * ND) + lane,       y0);
    __stcs((float4*)(out + (size_t)(gid0 + 1) * ND) + lane, y1);
}

static inline void launch_pdl(void* fn, dim3 grid, dim3 block, void** args) {
    cudaLaunchConfig_t cfg = {};
    cfg.gridDim = grid;
    cfg.blockDim = block;
    cfg.dynamicSmemBytes = 0;
    cfg.stream = 0;
    cudaLaunchAttribute attr[1];
    attr[0].id = cudaLaunchAttributeProgrammaticStreamSerialization;
    attr[0].val.programmaticStreamSerializationAllowed = 1;
    cfg.attrs = attr;
    cfg.numAttrs = 1;
    cudaLaunchKernelExC(&cfg, fn, args);
}

extern "C" void kernel_launch(void* const* d_in, const int* in_sizes, int n_in,
                              void* d_out, int out_size) {
    const float* x           = (const float*)d_in[0];
    const float* scales      = (const float*)d_in[1];
    const int*   len_seq     = (const int*)d_in[2];
    const int*   len_seg_raw = (const int*)d_in[3];
    float* out = (float*)d_out;

    setup_kernel<<<1, 1024>>>(scales, len_seq, len_seg_raw);

    void* args[] = { (void*)&x, (void*)&out };
    launch_pdl((void*)gather_kernel, dim3(NOUT / 2 / 8), dim3(256), args);
}